// round 2
// baseline (speedup 1.0000x reference)
#include <cuda_runtime.h>
#include <math_constants.h>

// ---------------------------------------------------------------------------
// Gaussian splatting forward, N=2048 gaussians -> 128x128x3 image.
// Pipeline: preprocess -> rank-sort+scatter -> chunked rasterize -> combine.
// ---------------------------------------------------------------------------

#define NG      2048
#define IMG_H   128
#define IMG_W   128
#define NPIX    (IMG_H * IMG_W)     // 16384
#define NCHUNK  8
#define CSZ     (NG / NCHUNK)       // 256

// Scratch (device globals; no allocations allowed)
__device__ float4 g_u0[NG];                 // unsorted {u, v, A2, B2}
__device__ float4 g_u1[NG];                 // unsorted {C2, op, r, g}
__device__ float  g_ub[NG];                 // unsorted b
__device__ float  g_key[NG];                // sort key (|pos_cam|^2, inf if masked)
__device__ float4 g_s0[NG];                 // sorted
__device__ float4 g_s1[NG];
__device__ float  g_sb[NG];
__device__ float4 g_part[NCHUNK * NPIX];    // per-chunk {r, g, b, T}

__device__ __forceinline__ void quat_to_rot(float w, float x, float y, float z, float* R) {
    float n = sqrtf(w*w + x*x + y*y + z*z) + 1e-12f;
    float inv = 1.0f / n;
    w *= inv; x *= inv; y *= inv; z *= inv;
    R[0] = 1.0f - 2.0f*(y*y + z*z);
    R[1] = 2.0f*(x*y - w*z);
    R[2] = 2.0f*(x*z + w*y);
    R[3] = 2.0f*(x*y + w*z);
    R[4] = 1.0f - 2.0f*(x*x + z*z);
    R[5] = 2.0f*(y*z - w*x);
    R[6] = 2.0f*(x*z - w*y);
    R[7] = 2.0f*(y*z + w*x);
    R[8] = 1.0f - 2.0f*(x*x + y*y);
}

// ---------------------------------------------------------------------------
// Kernel 1: per-gaussian preprocessing
// ---------------------------------------------------------------------------
__global__ void k_preprocess(const float* __restrict__ pos,
                             const float* __restrict__ rgb,
                             const float* __restrict__ opa,
                             const float* __restrict__ quat,
                             const float* __restrict__ scale,
                             const float* __restrict__ wq,
                             const float* __restrict__ wt) {
    int i = blockIdx.x * blockDim.x + threadIdx.x;
    if (i >= NG) return;

    float R[9];
    quat_to_rot(wq[0], wq[1], wq[2], wq[3], R);

    float px = pos[3*i], py = pos[3*i+1], pz = pos[3*i+2];
    // pos_cam = pos @ rot.T + t  ==  R * p + t
    float x = R[0]*px + R[1]*py + R[2]*pz + wt[0];
    float y = R[3]*px + R[4]*py + R[5]*pz + wt[1];
    float z = R[6]*px + R[7]*py + R[8]*pz + wt[2];
    float d2 = x*x + y*y + z*z;

    bool mask = z > 1.1f;                       // NEAR
    float zs = mask ? z : 1.0f;
    float u = x / zs;
    float v = y / zs;
    mask = mask && (fabsf(u) < 0.64f) && (fabsf(v) < 0.64f);   // W/(2FX) = 0.64

    float iz = 1.0f / zs;
    float iz2 = iz * iz;
    float J02 = -x * iz2, J12 = -y * iz2;       // J rows 0,1 (row 2 never reaches cov2d[:2,:2])
    float JW0[3], JW1[3];
    #pragma unroll
    for (int k = 0; k < 3; k++) {
        JW0[k] = iz * R[k]   + J02 * R[6+k];
        JW1[k] = iz * R[3+k] + J12 * R[6+k];
    }

    float Rg[9];
    quat_to_rot(quat[4*i], quat[4*i+1], quat[4*i+2], quat[4*i+3], Rg);
    float s0 = scale[3*i], s1 = scale[3*i+1], s2 = scale[3*i+2];
    float RS[9];
    #pragma unroll
    for (int r = 0; r < 3; r++) {
        RS[3*r+0] = Rg[3*r+0] * s0;
        RS[3*r+1] = Rg[3*r+1] * s1;
        RS[3*r+2] = Rg[3*r+2] * s2;
    }
    // cov3d = RS RS^T (symmetric)
    float c00 = RS[0]*RS[0] + RS[1]*RS[1] + RS[2]*RS[2];
    float c01 = RS[0]*RS[3] + RS[1]*RS[4] + RS[2]*RS[5];
    float c02 = RS[0]*RS[6] + RS[1]*RS[7] + RS[2]*RS[8];
    float c11 = RS[3]*RS[3] + RS[4]*RS[4] + RS[5]*RS[5];
    float c12 = RS[3]*RS[6] + RS[4]*RS[7] + RS[5]*RS[8];
    float c22 = RS[6]*RS[6] + RS[7]*RS[7] + RS[8]*RS[8];

    float M0x = JW0[0]*c00 + JW0[1]*c01 + JW0[2]*c02;
    float M0y = JW0[0]*c01 + JW0[1]*c11 + JW0[2]*c12;
    float M0z = JW0[0]*c02 + JW0[1]*c12 + JW0[2]*c22;
    float M1x = JW1[0]*c00 + JW1[1]*c01 + JW1[2]*c02;
    float M1y = JW1[0]*c01 + JW1[1]*c11 + JW1[2]*c12;
    float M1z = JW1[0]*c02 + JW1[1]*c12 + JW1[2]*c22;

    float a = M0x*JW0[0] + M0y*JW0[1] + M0z*JW0[2] + 1e-6f;
    float b = M0x*JW1[0] + M0y*JW1[1] + M0z*JW1[2];
    float c = M1x*JW1[0] + M1y*JW1[1] + M1z*JW1[2] + 1e-6f;

    float invdet = 1.0f / fmaxf(a*c - b*b, 1e-12f);
    // power = -0.5*(A dx^2 + C dy^2) + B dx dy ; A=c*invdet, B=b*invdet, C=a*invdet.
    // Fold -0.5 and log2(e) so rasterizer does ex2(min(A2 dx^2 + B2 dx dy + C2 dy^2, 0)).
    const float L2E = 1.4426950408889634f;
    float A2 = -0.5f * (c * invdet) * L2E;
    float B2 =         (b * invdet) * L2E;
    float C2 = -0.5f * (a * invdet) * L2E;

    float op = mask ? opa[i] : 0.0f;   // mask folded into opacity (all values finite)

    g_u0[i] = make_float4(u, v, A2, B2);
    g_u1[i] = make_float4(C2, op, rgb[3*i], rgb[3*i+1]);
    g_ub[i] = rgb[3*i+2];
    g_key[i] = mask ? d2 : CUDART_INF_F;   // d2 monotone in dnorm -> same order
}

// ---------------------------------------------------------------------------
// Kernel 2: stable rank sort (O(N^2) count) + scatter into sorted SoA
// ---------------------------------------------------------------------------
__global__ void k_sort_scatter() {
    __shared__ float keys[NG];
    for (int j = threadIdx.x; j < NG; j += blockDim.x) keys[j] = g_key[j];
    __syncthreads();

    int i = blockIdx.x * blockDim.x + threadIdx.x;
    float ki = keys[i];
    int rank = 0;
    #pragma unroll 8
    for (int j = 0; j < NG; j++) {
        float kj = keys[j];
        rank += (kj < ki) || (kj == ki && j < i);   // stable: index tiebreak (inf ties too)
    }
    g_s0[rank] = g_u0[i];
    g_s1[rank] = g_u1[i];
    g_sb[rank] = g_ub[i];
}

// ---------------------------------------------------------------------------
// Kernel 3: chunked rasterization. blockIdx.y = gaussian chunk.
// Each thread composites one pixel over its chunk of 256 sorted gaussians,
// producing partial RGB and the chunk's transmittance factor.
// ---------------------------------------------------------------------------
__global__ void __launch_bounds__(256) k_raster() {
    __shared__ float4 sm0[CSZ];
    __shared__ float4 sm1[CSZ];
    __shared__ float  smb[CSZ];

    int t = threadIdx.x;
    int chunk = blockIdx.y;
    int base = chunk * CSZ;
    sm0[t] = g_s0[base + t];
    sm1[t] = g_s1[base + t];
    smb[t] = g_sb[base + t];
    __syncthreads();

    int pix = blockIdx.x * 256 + t;
    int pi = pix >> 7;          // row (y)
    int pj = pix & 127;         // col (x)
    float pu = ((float)pj + 0.5f - 64.0f) / 100.0f;
    float pv = ((float)pi + 0.5f - 64.0f) / 100.0f;

    float T = 1.0f, cr = 0.0f, cg = 0.0f, cb = 0.0f;

    #pragma unroll 8
    for (int j = 0; j < CSZ; j++) {
        float4 p0 = sm0[j];
        float4 p1 = sm1[j];
        float  bb = smb[j];
        float dx = pu - p0.x;
        float dy = pv - p0.y;
        // power * log2(e), already includes -0.5 factors
        float pw = fmaf(dx, fmaf(p0.z, dx, p0.w * dy), p1.x * (dy * dy));
        pw = fminf(pw, 0.0f);
        float e;
        asm("ex2.approx.ftz.f32 %0, %1;" : "=f"(e) : "f"(pw));
        float alpha = fminf(p1.y * e, 0.99f);
        float w = T * alpha;
        cr = fmaf(w, p1.z, cr);
        cg = fmaf(w, p1.w, cg);
        cb = fmaf(w, bb, cb);
        T -= w;                 // T * (1 - alpha)
    }

    g_part[chunk * NPIX + pix] = make_float4(cr, cg, cb, T);
}

// ---------------------------------------------------------------------------
// Kernel 4: combine chunk partials in depth order
// ---------------------------------------------------------------------------
__global__ void k_combine(float* __restrict__ out) {
    int pix = blockIdx.x * blockDim.x + threadIdx.x;
    float T = 1.0f, r = 0.0f, g = 0.0f, b = 0.0f;
    #pragma unroll
    for (int c = 0; c < NCHUNK; c++) {
        float4 p = g_part[c * NPIX + pix];
        r = fmaf(T, p.x, r);
        g = fmaf(T, p.y, g);
        b = fmaf(T, p.z, b);
        T *= p.w;
    }
    out[3*pix + 0] = r;
    out[3*pix + 1] = g;
    out[3*pix + 2] = b;
}

// ---------------------------------------------------------------------------
extern "C" void kernel_launch(void* const* d_in, const int* in_sizes, int n_in,
                              void* d_out, int out_size) {
    const float* pos   = (const float*)d_in[0];
    const float* rgb   = (const float*)d_in[1];
    const float* opa   = (const float*)d_in[2];
    const float* quat  = (const float*)d_in[3];
    const float* scale = (const float*)d_in[4];
    const float* wq    = (const float*)d_in[5];
    const float* wt    = (const float*)d_in[6];
    float* out = (float*)d_out;

    k_preprocess<<<NG / 256, 256>>>(pos, rgb, opa, quat, scale, wq, wt);
    k_sort_scatter<<<NG / 256, 256>>>();
    k_raster<<<dim3(NPIX / 256, NCHUNK), 256>>>();
    k_combine<<<NPIX / 256, 256>>>(out);
}

// round 3
// speedup vs baseline: 1.3922x; 1.3922x over previous
#include <cuda_runtime.h>
#include <math_constants.h>

// ---------------------------------------------------------------------------
// Gaussian splatting forward, N=2048 gaussians -> 128x128x3 image.
// Pipeline: preprocess (+bbox) -> rank-sort+scatter -> tile-culled rasterize.
// ---------------------------------------------------------------------------

#define NG      2048
#define IMG_H   128
#define IMG_W   128
#define NPIX    (IMG_H * IMG_W)     // 16384
#define TILE    16
#define TILES_X (IMG_W / TILE)      // 8
#define TILES_Y (IMG_H / TILE)      // 8

// Cull threshold: skip where power*log2e < -TAU  (alpha <= opa * 2^-TAU)
#define TAU     32.0f

// Scratch (device globals; no allocations allowed)
__device__ float4 g_u0[NG];                 // unsorted {u, v, A2, B2}
__device__ float4 g_u1[NG];                 // unsorted {C2, op, r, g}
__device__ float  g_ub[NG];                 // unsorted b
__device__ float2 g_ubb[NG];                // unsorted bbox half-extents {bx, by}
__device__ float  g_key[NG];                // sort key (|pos_cam|^2, inf if masked)
__device__ float4 g_s0[NG];                 // sorted
__device__ float4 g_s1[NG];
__device__ float  g_sb[NG];
__device__ float2 g_sbb[NG];

__device__ __forceinline__ void quat_to_rot(float w, float x, float y, float z, float* R) {
    float n = sqrtf(w*w + x*x + y*y + z*z) + 1e-12f;
    float inv = 1.0f / n;
    w *= inv; x *= inv; y *= inv; z *= inv;
    R[0] = 1.0f - 2.0f*(y*y + z*z);
    R[1] = 2.0f*(x*y - w*z);
    R[2] = 2.0f*(x*z + w*y);
    R[3] = 2.0f*(x*y + w*z);
    R[4] = 1.0f - 2.0f*(x*x + z*z);
    R[5] = 2.0f*(y*z - w*x);
    R[6] = 2.0f*(x*z - w*y);
    R[7] = 2.0f*(y*z + w*x);
    R[8] = 1.0f - 2.0f*(x*x + y*y);
}

// ---------------------------------------------------------------------------
// Kernel 1: per-gaussian preprocessing (+ conservative bbox)
// ---------------------------------------------------------------------------
__global__ void k_preprocess(const float* __restrict__ pos,
                             const float* __restrict__ rgb,
                             const float* __restrict__ opa,
                             const float* __restrict__ quat,
                             const float* __restrict__ scale,
                             const float* __restrict__ wq,
                             const float* __restrict__ wt) {
    int i = blockIdx.x * blockDim.x + threadIdx.x;
    if (i >= NG) return;

    float R[9];
    quat_to_rot(wq[0], wq[1], wq[2], wq[3], R);

    float px = pos[3*i], py = pos[3*i+1], pz = pos[3*i+2];
    float x = R[0]*px + R[1]*py + R[2]*pz + wt[0];
    float y = R[3]*px + R[4]*py + R[5]*pz + wt[1];
    float z = R[6]*px + R[7]*py + R[8]*pz + wt[2];
    float d2 = x*x + y*y + z*z;

    bool mask = z > 1.1f;                       // NEAR
    float zs = mask ? z : 1.0f;
    float u = x / zs;
    float v = y / zs;
    mask = mask && (fabsf(u) < 0.64f) && (fabsf(v) < 0.64f);   // W/(2FX)

    float iz = 1.0f / zs;
    float iz2 = iz * iz;
    float J02 = -x * iz2, J12 = -y * iz2;
    float JW0[3], JW1[3];
    #pragma unroll
    for (int k = 0; k < 3; k++) {
        JW0[k] = iz * R[k]   + J02 * R[6+k];
        JW1[k] = iz * R[3+k] + J12 * R[6+k];
    }

    float Rg[9];
    quat_to_rot(quat[4*i], quat[4*i+1], quat[4*i+2], quat[4*i+3], Rg);
    float s0 = scale[3*i], s1 = scale[3*i+1], s2 = scale[3*i+2];
    float RS[9];
    #pragma unroll
    for (int r = 0; r < 3; r++) {
        RS[3*r+0] = Rg[3*r+0] * s0;
        RS[3*r+1] = Rg[3*r+1] * s1;
        RS[3*r+2] = Rg[3*r+2] * s2;
    }
    float c00 = RS[0]*RS[0] + RS[1]*RS[1] + RS[2]*RS[2];
    float c01 = RS[0]*RS[3] + RS[1]*RS[4] + RS[2]*RS[5];
    float c02 = RS[0]*RS[6] + RS[1]*RS[7] + RS[2]*RS[8];
    float c11 = RS[3]*RS[3] + RS[4]*RS[4] + RS[5]*RS[5];
    float c12 = RS[3]*RS[6] + RS[4]*RS[7] + RS[5]*RS[8];
    float c22 = RS[6]*RS[6] + RS[7]*RS[7] + RS[8]*RS[8];

    float M0x = JW0[0]*c00 + JW0[1]*c01 + JW0[2]*c02;
    float M0y = JW0[0]*c01 + JW0[1]*c11 + JW0[2]*c12;
    float M0z = JW0[0]*c02 + JW0[1]*c12 + JW0[2]*c22;
    float M1x = JW1[0]*c00 + JW1[1]*c01 + JW1[2]*c02;
    float M1y = JW1[0]*c01 + JW1[1]*c11 + JW1[2]*c12;
    float M1z = JW1[0]*c02 + JW1[1]*c12 + JW1[2]*c22;

    float a = M0x*JW0[0] + M0y*JW0[1] + M0z*JW0[2] + 1e-6f;
    float b = M0x*JW1[0] + M0y*JW1[1] + M0z*JW1[2];
    float c = M1x*JW1[0] + M1y*JW1[1] + M1z*JW1[2] + 1e-6f;

    float invdet = 1.0f / fmaxf(a*c - b*b, 1e-12f);
    float Ap = c * invdet;       // conic entries (natural scale)
    float Bp = b * invdet;
    float Cp = a * invdet;

    // Rasterizer evaluates pw2 = A2 dx^2 + B2 dx dy + C2 dy^2 (log2 domain)
    const float L2E = 1.4426950408889634f;
    float A2 = -0.5f * Ap * L2E;
    float B2 =         Bp * L2E;
    float C2 = -0.5f * Cp * L2E;

    // Conservative bbox of {pw2 >= -TAU}: quadratic form M=[Ap -Bp; -Bp Cp],
    // region d^T M d <= 2t with t = TAU/L2E. |dx| <= sqrt(2t*Cp/detM).
    float detM = (a*c - b*b) * invdet * invdet;
    float twot = 2.0f * (TAU / L2E);
    float bx, by;
    if (detM > 0.0f && isfinite(detM)) {
        float inv_dm = 1.02f / detM;                   // 2% fp safety margin
        bx = sqrtf(fmaxf(twot * Cp * inv_dm, 0.0f));
        by = sqrtf(fmaxf(twot * Ap * inv_dm, 0.0f));
        if (!isfinite(bx) || !isfinite(by)) { bx = 1e9f; by = 1e9f; }
    } else {
        bx = 1e9f; by = 1e9f;                          // not pos-def: never cull
    }
    if (!mask) { bx = -1e9f; by = -1e9f; }             // masked: always cull (exact)

    float op = mask ? opa[i] : 0.0f;

    g_u0[i]  = make_float4(u, v, A2, B2);
    g_u1[i]  = make_float4(C2, op, rgb[3*i], rgb[3*i+1]);
    g_ub[i]  = rgb[3*i+2];
    g_ubb[i] = make_float2(bx, by);
    g_key[i] = mask ? d2 : CUDART_INF_F;
}

// ---------------------------------------------------------------------------
// Kernel 2: stable rank sort (O(N^2) count) + scatter into sorted SoA
// ---------------------------------------------------------------------------
__global__ void k_sort_scatter() {
    __shared__ float keys[NG];
    for (int j = threadIdx.x; j < NG; j += blockDim.x) keys[j] = g_key[j];
    __syncthreads();

    int i = blockIdx.x * blockDim.x + threadIdx.x;
    float ki = keys[i];
    int rank = 0;
    #pragma unroll 8
    for (int j = 0; j < NG; j++) {
        float kj = keys[j];
        rank += (kj < ki) || (kj == ki && j < i);   // stable via index tiebreak
    }
    g_s0[rank]  = g_u0[i];
    g_s1[rank]  = g_u1[i];
    g_sb[rank]  = g_ub[i];
    g_sbb[rank] = g_ubb[i];
}

// ---------------------------------------------------------------------------
// Kernel 3: tile-culled rasterization. One block per 16x16 tile (64 blocks).
// Phase A: order-preserving compaction of gaussians whose bbox overlaps tile.
// Phase B: composite over the compact list in depth order, staged via smem.
// ---------------------------------------------------------------------------
__global__ void __launch_bounds__(256) k_tile_raster(float* __restrict__ out) {
    __shared__ unsigned short s_list[NG];
    __shared__ int  s_wcnt[8];
    __shared__ float4 sc0[256];
    __shared__ float4 sc1[256];
    __shared__ float  scb[256];

    int t = threadIdx.x;
    int lane = t & 31, wid = t >> 5;
    int tx = blockIdx.x & (TILES_X - 1);
    int ty = blockIdx.x / TILES_X;

    // Tile pixel-center ranges in u/v space
    float ulo = ((float)(tx * TILE) + 0.5f  - 64.0f) * 0.01f;
    float uhi = ((float)(tx * TILE) + 15.5f - 64.0f) * 0.01f;
    float vlo = ((float)(ty * TILE) + 0.5f  - 64.0f) * 0.01f;
    float vhi = ((float)(ty * TILE) + 15.5f - 64.0f) * 0.01f;

    // ---- Phase A: compaction (preserves sorted depth order) ----
    int cnt = 0;
    #pragma unroll
    for (int c = 0; c < NG / 256; c++) {
        int g = c * 256 + t;
        float4 p0 = g_s0[g];
        float2 bb = g_sbb[g];
        bool keep = (p0.x + bb.x >= ulo) && (p0.x - bb.x <= uhi) &&
                    (p0.y + bb.y >= vlo) && (p0.y - bb.y <= vhi);
        unsigned m = __ballot_sync(0xffffffffu, keep);
        if (lane == 0) s_wcnt[wid] = __popc(m);
        __syncthreads();
        int wbase = 0, tot = 0;
        #pragma unroll
        for (int k = 0; k < 8; k++) {
            int wc = s_wcnt[k];
            if (k < wid) wbase += wc;
            tot += wc;
        }
        if (keep) {
            int rank = cnt + wbase + __popc(m & ((1u << lane) - 1u));
            s_list[rank] = (unsigned short)g;
        }
        cnt += tot;
        __syncthreads();
    }
    int L = cnt;

    // ---- Phase B: composite ----
    int pi = ty * TILE + (t >> 4);
    int pj = tx * TILE + (t & 15);
    float pu = ((float)pj + 0.5f - 64.0f) * 0.01f;
    float pv = ((float)pi + 0.5f - 64.0f) * 0.01f;

    float T = 1.0f, cr = 0.0f, cg = 0.0f, cb = 0.0f;

    for (int base = 0; base < L; base += 256) {
        int n = min(256, L - base);
        if (t < n) {
            int g = s_list[base + t];
            sc0[t] = g_s0[g];
            sc1[t] = g_s1[g];
            scb[t] = g_sb[g];
        }
        __syncthreads();

        #pragma unroll 4
        for (int j = 0; j < n; j++) {
            float4 p0 = sc0[j];
            float4 p1 = sc1[j];
            float  bb = scb[j];
            float dx = pu - p0.x;
            float dy = pv - p0.y;
            float pw = fmaf(dx, fmaf(p0.z, dx, p0.w * dy), p1.x * (dy * dy));
            pw = fminf(pw, 0.0f);
            float e;
            asm("ex2.approx.ftz.f32 %0, %1;" : "=f"(e) : "f"(pw));
            float alpha = fminf(p1.y * e, 0.99f);
            float w = T * alpha;
            cr = fmaf(w, p1.z, cr);
            cg = fmaf(w, p1.w, cg);
            cb = fmaf(w, bb, cb);
            T -= w;
        }
        // Block-uniform early exit: remaining contribution bounded by T
        if (__syncthreads_and(T < 1e-7f)) break;
        __syncthreads();
    }

    int pix = pi * IMG_W + pj;
    out[3*pix + 0] = cr;
    out[3*pix + 1] = cg;
    out[3*pix + 2] = cb;
}

// ---------------------------------------------------------------------------
extern "C" void kernel_launch(void* const* d_in, const int* in_sizes, int n_in,
                              void* d_out, int out_size) {
    const float* pos   = (const float*)d_in[0];
    const float* rgb   = (const float*)d_in[1];
    const float* opa   = (const float*)d_in[2];
    const float* quat  = (const float*)d_in[3];
    const float* scale = (const float*)d_in[4];
    const float* wq    = (const float*)d_in[5];
    const float* wt    = (const float*)d_in[6];
    float* out = (float*)d_out;

    k_preprocess<<<NG / 256, 256>>>(pos, rgb, opa, quat, scale, wq, wt);
    k_sort_scatter<<<NG / 256, 256>>>();
    k_tile_raster<<<TILES_X * TILES_Y, 256>>>(out);
}

// round 5
// speedup vs baseline: 2.6250x; 1.8855x over previous
#include <cuda_runtime.h>
#include <math_constants.h>

// ---------------------------------------------------------------------------
// Gaussian splatting forward, N=2048 -> 128x128x3. Single fused kernel:
//   preprocess -> gridbar -> rank-sort+scatter -> gridbar -> tile raster.
// 64 blocks x 256 threads (all co-resident on 148 SMs -> spin barrier safe).
// ---------------------------------------------------------------------------

#define NG      2048
#define IMG     128
#define TILE    16
#define TILES_X 8
#define NBLK    64
#define TPB     256
#define TAU     32.0f    // skip where power*log2e < -TAU

// Device scratch
__device__ float4 g_u0[NG];      // {u, v, A2, B2}
__device__ float4 g_u1[NG];      // {C2, op, r, g}
__device__ float  g_ub[NG];      // b
__device__ float2 g_ubb[NG];     // bbox half extents
__device__ float  g_key[NG];
__device__ float4 g_s0[NG];
__device__ float4 g_s1[NG];
__device__ float  g_sb[NG];
__device__ float2 g_sbb[NG];
__device__ unsigned g_bar;       // monotone grid-barrier counter (zero-init)

__device__ __forceinline__ float frcp(float x)   { float r; asm("rcp.approx.ftz.f32 %0,%1;"  :"=f"(r):"f"(x)); return r; }
__device__ __forceinline__ float frsqrt(float x) { float r; asm("rsqrt.approx.ftz.f32 %0,%1;":"=f"(r):"f"(x)); return r; }
__device__ __forceinline__ float fex2(float x)   { float r; asm("ex2.approx.ftz.f32 %0,%1;"  :"=f"(r):"f"(x)); return r; }

// Monotone-counter grid barrier. Well-nested: arrivals for barrier instance p
// are tickets [64p, 64p+64), so target = (ticket/64 + 1)*64. Replay-safe.
__device__ __forceinline__ void grid_barrier() {
    __syncthreads();
    __threadfence();
    if (threadIdx.x == 0) {
        unsigned tk = atomicAdd(&g_bar, 1u);
        unsigned target = ((tk >> 6) + 1u) << 6;
        while (*(volatile unsigned*)&g_bar < target) { }
    }
    __syncthreads();
    __threadfence();
}

__device__ __forceinline__ void quat_to_rot(float w, float x, float y, float z, float* R) {
    float inv = frsqrt(w*w + x*x + y*y + z*z);
    w *= inv; x *= inv; y *= inv; z *= inv;
    R[0] = 1.0f - 2.0f*(y*y + z*z);
    R[1] = 2.0f*(x*y - w*z);
    R[2] = 2.0f*(x*z + w*y);
    R[3] = 2.0f*(x*y + w*z);
    R[4] = 1.0f - 2.0f*(x*x + z*z);
    R[5] = 2.0f*(y*z - w*x);
    R[6] = 2.0f*(x*z - w*y);
    R[7] = 2.0f*(y*z + w*x);
    R[8] = 1.0f - 2.0f*(x*x + y*y);
}

// Shared memory plan (aliased across phases, separated by grid_barrier):
//  Phase 2: [0,8192) keys (float x2048), [8192,9216) partial ranks (int 8x32)
//  Phase 3: [0,4096) list (u16 x2048), [4096,8192) sc0, [8192,12288) sc1,
//           [12288,13312) scb, [13312,13568) cnt (int 64)
#define SMEM_BYTES 13568

__global__ void __launch_bounds__(TPB, 1) k_fused(
        const float* __restrict__ pos,  const float* __restrict__ rgb,
        const float* __restrict__ opa,  const float* __restrict__ quat,
        const float* __restrict__ scale,const float* __restrict__ wq,
        const float* __restrict__ wt,   float* __restrict__ out) {
    __shared__ __align__(16) unsigned char sraw[SMEM_BYTES];

    const int t = threadIdx.x;
    const int b = blockIdx.x;
    const int lane = t & 31;
    const int wid  = t >> 5;

    // ===================== Phase 1: preprocess (warp 0) =====================
    if (t < 32) {
        int i = b * 32 + t;

        float R[9];
        quat_to_rot(wq[0], wq[1], wq[2], wq[3], R);

        float px = pos[3*i], py = pos[3*i+1], pz = pos[3*i+2];
        float x = R[0]*px + R[1]*py + R[2]*pz + wt[0];
        float y = R[3]*px + R[4]*py + R[5]*pz + wt[1];
        float z = R[6]*px + R[7]*py + R[8]*pz + wt[2];
        float d2 = x*x + y*y + z*z;

        bool mask = z > 1.1f;
        float zs = mask ? z : 1.0f;
        float iz = frcp(zs);
        float u = x * iz;
        float v = y * iz;
        mask = mask && (fabsf(u) < 0.64f) && (fabsf(v) < 0.64f);

        float iz2 = iz * iz;
        float J02 = -x * iz2, J12 = -y * iz2;
        float JW0[3], JW1[3];
        #pragma unroll
        for (int k = 0; k < 3; k++) {
            JW0[k] = iz * R[k]   + J02 * R[6+k];
            JW1[k] = iz * R[3+k] + J12 * R[6+k];
        }

        float Rg[9];
        quat_to_rot(quat[4*i], quat[4*i+1], quat[4*i+2], quat[4*i+3], Rg);
        float s0 = scale[3*i], s1 = scale[3*i+1], s2 = scale[3*i+2];
        float RS[9];
        #pragma unroll
        for (int r = 0; r < 3; r++) {
            RS[3*r+0] = Rg[3*r+0] * s0;
            RS[3*r+1] = Rg[3*r+1] * s1;
            RS[3*r+2] = Rg[3*r+2] * s2;
        }
        float c00 = RS[0]*RS[0] + RS[1]*RS[1] + RS[2]*RS[2];
        float c01 = RS[0]*RS[3] + RS[1]*RS[4] + RS[2]*RS[5];
        float c02 = RS[0]*RS[6] + RS[1]*RS[7] + RS[2]*RS[8];
        float c11 = RS[3]*RS[3] + RS[4]*RS[4] + RS[5]*RS[5];
        float c12 = RS[3]*RS[6] + RS[4]*RS[7] + RS[5]*RS[8];
        float c22 = RS[6]*RS[6] + RS[7]*RS[7] + RS[8]*RS[8];

        float M0x = JW0[0]*c00 + JW0[1]*c01 + JW0[2]*c02;
        float M0y = JW0[0]*c01 + JW0[1]*c11 + JW0[2]*c12;
        float M0z = JW0[0]*c02 + JW0[1]*c12 + JW0[2]*c22;
        float M1x = JW1[0]*c00 + JW1[1]*c01 + JW1[2]*c02;
        float M1y = JW1[0]*c01 + JW1[1]*c11 + JW1[2]*c12;
        float M1z = JW1[0]*c02 + JW1[1]*c12 + JW1[2]*c22;

        float a = M0x*JW0[0] + M0y*JW0[1] + M0z*JW0[2] + 1e-6f;
        float bq= M0x*JW1[0] + M0y*JW1[1] + M0z*JW1[2];
        float c = M1x*JW1[0] + M1y*JW1[1] + M1z*JW1[2] + 1e-6f;

        float det = fmaxf(a*c - bq*bq, 1e-12f);
        float invdet = frcp(det);
        float Ap = c  * invdet;
        float Bp = bq * invdet;
        float Cp = a  * invdet;

        const float L2E = 1.4426950408889634f;
        float A2 = -0.5f * Ap * L2E;
        float B2 =         Bp * L2E;
        float C2 = -0.5f * Cp * L2E;

        // Conservative bbox of {quadratic <= 2t}: |dx| <= sqrt(2t*Cp/detM)
        float detM = det * invdet * invdet;
        float twot = 2.0f * (TAU / L2E);
        float bx, by;
        if (detM > 0.0f && isfinite(detM)) {
            float inv_dm = 1.02f * frcp(detM);
            bx = sqrtf(fmaxf(twot * Cp * inv_dm, 0.0f));
            by = sqrtf(fmaxf(twot * Ap * inv_dm, 0.0f));
            if (!isfinite(bx) || !isfinite(by)) { bx = 1e9f; by = 1e9f; }
        } else {
            bx = 1e9f; by = 1e9f;
        }
        if (!mask) { bx = -1e9f; by = -1e9f; }    // always culled (alpha=0 anyway)

        float op = mask ? opa[i] : 0.0f;

        g_u0[i]  = make_float4(u, v, A2, B2);
        g_u1[i]  = make_float4(C2, op, rgb[3*i], rgb[3*i+1]);
        g_ub[i]  = rgb[3*i+2];
        g_ubb[i] = make_float2(bx, by);
        g_key[i] = mask ? d2 : CUDART_INF_F;
    }

    grid_barrier();

    // ===================== Phase 2: stable rank sort ========================
    {
        float* s_keys = (float*)sraw;                    // 2048 floats
        int*   s_part = (int*)(sraw + 8192);             // 8 x 32

        #pragma unroll
        for (int c = 0; c < 8; c++) s_keys[c*256 + t] = g_key[c*256 + t];
        __syncthreads();

        int i = b * 32 + lane;                // gaussian owned by this lane
        float ki = s_keys[i];
        int part = 0;
        int j0 = wid * 256;
        #pragma unroll 8
        for (int j = j0; j < j0 + 256; j++) {
            float kj = s_keys[j];
            part += (kj < ki) || (kj == ki && j < i);    // stable tiebreak
        }
        s_part[wid*32 + lane] = part;
        __syncthreads();

        if (t < 32) {
            int i2 = b * 32 + t;
            int rank = 0;
            #pragma unroll
            for (int w2 = 0; w2 < 8; w2++) rank += s_part[w2*32 + t];
            g_s0[rank]  = g_u0[i2];
            g_s1[rank]  = g_u1[i2];
            g_sb[rank]  = g_ub[i2];
            g_sbb[rank] = g_ubb[i2];
        }
    }

    grid_barrier();

    // ===================== Phase 3: tile raster =============================
    {
        unsigned short* s_list = (unsigned short*)sraw;          // 2048
        float4* sc0 = (float4*)(sraw + 4096);                    // 256
        float4* sc1 = (float4*)(sraw + 8192);                    // 256
        float*  scb = (float*)(sraw + 12288);                    // 256
        int*    s_cnt = (int*)(sraw + 13312);                    // 8x8 [c][w]

        int tx = b & (TILES_X - 1);
        int ty = b / TILES_X;

        float ulo = ((float)(tx * TILE) + 0.5f  - 64.0f) * 0.01f;
        float uhi = ((float)(tx * TILE) + 15.5f - 64.0f) * 0.01f;
        float vlo = ((float)(ty * TILE) + 0.5f  - 64.0f) * 0.01f;
        float vhi = ((float)(ty * TILE) + 15.5f - 64.0f) * 0.01f;

        // --- Phase A: ordered compaction, ballots held in registers ---
        unsigned mk[8];
        #pragma unroll
        for (int c = 0; c < 8; c++) {
            int g = c * 256 + t;
            float4 p0 = g_s0[g];
            float2 bb = g_sbb[g];
            bool keep = (p0.x + bb.x >= ulo) && (p0.x - bb.x <= uhi) &&
                        (p0.y + bb.y >= vlo) && (p0.y - bb.y <= vhi);
            mk[c] = __ballot_sync(0xffffffffu, keep);
            if (lane == 0) s_cnt[c*8 + wid] = __popc(mk[c]);
        }
        __syncthreads();

        int off[8];
        int run = 0;
        #pragma unroll
        for (int c = 0; c < 8; c++) {
            int myb = run, tot = 0;
            #pragma unroll
            for (int w2 = 0; w2 < 8; w2++) {
                int vcnt = s_cnt[c*8 + w2];
                if (w2 < wid) myb += vcnt;
                tot += vcnt;
            }
            off[c] = myb;
            run += tot;
        }
        int L = run;

        unsigned lmask = (1u << lane) - 1u;
        #pragma unroll
        for (int c = 0; c < 8; c++) {
            if (mk[c] & (1u << lane)) {
                int posn = off[c] + __popc(mk[c] & lmask);
                s_list[posn] = (unsigned short)(c * 256 + t);
            }
        }
        __syncthreads();

        // --- Phase B: composite in depth order, chunked through smem ---
        int pi = ty * TILE + (t >> 4);
        int pj = tx * TILE + (t & 15);
        float pu = ((float)pj + 0.5f - 64.0f) * 0.01f;
        float pv = ((float)pi + 0.5f - 64.0f) * 0.01f;

        float T = 1.0f, cr = 0.0f, cg = 0.0f, cb = 0.0f;

        for (int base = 0; base < L; base += 256) {
            int n = min(256, L - base);
            if (t < n) {
                int g = s_list[base + t];
                sc0[t] = g_s0[g];
                sc1[t] = g_s1[g];
                scb[t] = g_sb[g];
            }
            __syncthreads();

            #pragma unroll 4
            for (int j = 0; j < n; j++) {
                float4 p0 = sc0[j];
                float4 p1 = sc1[j];
                float  bb = scb[j];
                float dx = pu - p0.x;
                float dy = pv - p0.y;
                float pw = fmaf(dx, fmaf(p0.z, dx, p0.w * dy), p1.x * (dy * dy));
                pw = fminf(pw, 0.0f);
                float e = fex2(pw);
                float alpha = fminf(p1.y * e, 0.99f);
                float w = T * alpha;
                cr = fmaf(w, p1.z, cr);
                cg = fmaf(w, p1.w, cg);
                cb = fmaf(w, bb, cb);
                T -= w;
            }
            if (__syncthreads_and(T < 1e-7f)) break;   // full barrier too
        }

        int pix = pi * IMG + pj;
        out[3*pix + 0] = cr;
        out[3*pix + 1] = cg;
        out[3*pix + 2] = cb;
    }
}

// ---------------------------------------------------------------------------
extern "C" void kernel_launch(void* const* d_in, const int* in_sizes, int n_in,
                              void* d_out, int out_size) {
    const float* pos   = (const float*)d_in[0];
    const float* rgb   = (const float*)d_in[1];
    const float* opa   = (const float*)d_in[2];
    const float* quat  = (const float*)d_in[3];
    const float* scale = (const float*)d_in[4];
    const float* wq    = (const float*)d_in[5];
    const float* wt    = (const float*)d_in[6];
    float* out = (float*)d_out;

    k_fused<<<NBLK, TPB>>>(pos, rgb, opa, quat, scale, wq, wt, out);
}